// round 13
// baseline (speedup 1.0000x reference)
#include <cuda_runtime.h>
#include <cuda_bf16.h>
#include <cstdint>

#define N_NODES 500000
#define N_ELEM  1000000
#define N_G2    (N_ELEM / 2)          // 500000 element pairs
#define N_NG4   (N_NODES / 4)         // 125000 node groups of 4

#define TPB   256
#define GRID  296                     // 148 SMs * 2 blocks -> all co-resident
#define NTH   (GRID * TPB)            // 75776 threads
#define NITER ((N_G2 + NTH - 1) / NTH) // 7 (compile-time)
#define DEPTH 2                       // cp.async double buffer

// Packed, pre-scaled node displacements (u_phys), 16B/node.
__device__ float4 g_pred4[N_NODES];               // 8 MB scratch
__device__ double g_partials[GRID];
__device__ unsigned int g_bar;    // barrier arrive counter (reset in-kernel)
__device__ unsigned int g_gen;    // barrier generation (monotonic across replays)
__device__ unsigned int g_count;  // finalize counter (reset in-kernel)

__device__ __forceinline__ double block_reduce_add(double v) {
    __shared__ double warp_sums[TPB / 32];
    int lane = threadIdx.x & 31;
    int wid  = threadIdx.x >> 5;

    #pragma unroll
    for (int off = 16; off > 0; off >>= 1)
        v += __shfl_down_sync(0xFFFFFFFFu, v, off);

    if (lane == 0) warp_sums[wid] = v;
    __syncthreads();

    v = (threadIdx.x < (TPB / 32)) ? warp_sums[threadIdx.x] : 0.0;
    if (wid == 0) {
        #pragma unroll
        for (int off = (TPB / 64); off > 0; off >>= 1)
            v += __shfl_down_sync(0xFFFFFFFFu, v, off);
    }
    __syncthreads();
    return v; // valid in thread 0
}

// ---- element-phase structs / helpers ----
struct Stream {
    int4   cab;          // nA0,nB0,nA1,nB1
    float2 L, E, A, I;
    float2 D0, D1, D2;   // (c0,0) (s0,c1) (0,s1)
    float  w;            // validity mask
};
struct Gath { float4 A0, B0, A1, B1; };

__device__ __forceinline__ Stream load_stream(
    int g,
    const int4* __restrict__ c4,
    const float2* __restrict__ L2p, const float2* __restrict__ E2p,
    const float2* __restrict__ A2p, const float2* __restrict__ I2p,
    const float2* __restrict__ d2p)
{
    Stream S;
    bool v = (g < N_G2);
    int gg = v ? g : 0;
    S.cab = __ldg(&c4[gg]);
    S.L   = __ldg(&L2p[gg]);
    S.E   = __ldg(&E2p[gg]);
    S.A   = __ldg(&A2p[gg]);
    S.I   = __ldg(&I2p[gg]);
    S.D0  = __ldg(&d2p[3 * gg + 0]);
    S.D1  = __ldg(&d2p[3 * gg + 1]);
    S.D2  = __ldg(&d2p[3 * gg + 2]);
    S.w   = v ? 1.0f : 0.0f;
    return S;
}

// cp.async.cg: 16B global->shared via L2 (coherent with this launch's stores),
// completion tracked by commit-groups -> no scoreboard slot, no register hold.
__device__ __forceinline__ void cp_async16(unsigned int dst_smem, const float4* src) {
    asm volatile("cp.async.cg.shared.global [%0], [%1], 16;"
                 :: "r"(dst_smem), "l"(src));
}

__device__ __forceinline__ float one_elem(
    float c, float s, float4 PA, float4 PB,
    float L, float E, float A, float I)
{
    float uA =  c * PA.x + s * PA.y;
    float wA = -s * PA.x + c * PA.y;
    float uB =  c * PB.x + s * PB.y;
    float wB = -s * PB.x + c * PB.y;
    float tA = PA.z, tB = PB.z;

    float EA = E * A;
    float EI = E * I;
    float invL  = 1.0f / L;
    float ea_L  = EA * invL;
    float ei_L  = EI * invL;
    float ei_L2 = ei_L * invL;
    float ei_L3 = ei_L2 * invL;

    float du = uA - uB;
    float dw = wA - wB;
    float ts = tA + tB;

    return ea_L * du * du
         + 12.0f * ei_L3 * dw * dw
         + 12.0f * ei_L2 * dw * ts
         + 4.0f  * ei_L  * (tA * tA + tB * tB + tA * tB);
}

__device__ __forceinline__ float pair_energy(const Stream& S, const Gath& G) {
    float q = one_elem(S.D0.x, S.D1.x, G.A0, G.B0, S.L.x, S.E.x, S.A.x, S.I.x)
            + one_elem(S.D1.y, S.D2.y, G.A1, G.B1, S.L.y, S.E.y, S.A.y, S.I.y);
    return q * S.w;
}

__global__ void __launch_bounds__(TPB, 2)
fused_energy_kernel(
    const float* __restrict__ pred,   // [N_NODES,3]
    const float* __restrict__ Lv,
    const float* __restrict__ Ev,
    const float* __restrict__ Av,
    const float* __restrict__ Iv,
    const float* __restrict__ dir,    // [N_ELEM,3]
    const int*   __restrict__ conn,   // [N_ELEM,2]
    const float* __restrict__ Fext,   // [N_NODES,3]
    const float* __restrict__ u_c_p,
    const float* __restrict__ th_c_p,
    const float* __restrict__ F_c_p,
    float*       __restrict__ out)
{
    // Gather staging: layout [stage*4 + k][tid] -> 16B lane stride (<=4-way bank).
    __shared__ float4 gbuf[DEPTH * 4 * TPB];   // 32 KB

    const float u_c  = __ldg(u_c_p);
    const float th_c = __ldg(th_c_p);

    const int tid = blockIdx.x * TPB + threadIdx.x;

    double acc = 0.0;   // -W_ext contribution; energy added at end

    // ---------------- Phase 1: pack nodes + external work ----------------
    {
        const float4* p4 = (const float4*)pred;
        const float4* f4 = (const float4*)Fext;

        for (int t = tid; t < N_NG4; t += NTH) {
            float4 P0 = __ldg(&p4[3 * t + 0]);  // x0 y0 t0 x1
            float4 P1 = __ldg(&p4[3 * t + 1]);  // y1 t1 x2 y2
            float4 P2 = __ldg(&p4[3 * t + 2]);  // t2 x3 y3 t3
            float4 F0 = __ldg(&f4[3 * t + 0]);
            float4 F1 = __ldg(&f4[3 * t + 1]);
            float4 F2 = __ldg(&f4[3 * t + 2]);

            float4 n0 = make_float4(P0.x * u_c, P0.y * u_c, P0.z * th_c, 0.0f);
            float4 n1 = make_float4(P0.w * u_c, P1.x * u_c, P1.y * th_c, 0.0f);
            float4 n2 = make_float4(P1.z * u_c, P1.w * u_c, P2.x * th_c, 0.0f);
            float4 n3 = make_float4(P2.y * u_c, P2.z * u_c, P2.w * th_c, 0.0f);

            int n = 4 * t;
            g_pred4[n + 0] = n0;
            g_pred4[n + 1] = n1;
            g_pred4[n + 2] = n2;
            g_pred4[n + 3] = n3;

            float w = F0.x * n0.x + F0.y * n0.y + F0.z * n0.z
                    + F0.w * n1.x + F1.x * n1.y + F1.y * n1.z
                    + F1.z * n2.x + F1.w * n2.y + F2.x * n2.z
                    + F2.y * n3.x + F2.z * n3.y + F2.w * n3.z;
            acc -= (double)w;
        }
    }

    // ---------------- Prefetch phase-2 streams (pack-independent) --------
    const int4*   c4  = (const int4*)conn;
    const float2* L2p = (const float2*)Lv;
    const float2* E2p = (const float2*)Ev;
    const float2* A2p = (const float2*)Av;
    const float2* I2p = (const float2*)Iv;
    const float2* d2p = (const float2*)dir;

    Stream s_cur = load_stream(tid,       c4, L2p, E2p, A2p, I2p, d2p);
    Stream s_nxt = load_stream(tid + NTH, c4, L2p, E2p, A2p, I2p, d2p);

    // ---------------- Grid-wide barrier (all 296 blocks co-resident) -----
    __syncthreads();                 // whole block done with phase-1 stores
    __shared__ unsigned int bar_gen;
    if (threadIdx.x == 0) {
        __threadfence();             // publish g_pred4 stores to L2
        unsigned int start = *(volatile unsigned int*)&g_gen;
        unsigned int old = atomicAdd(&g_bar, 1u);
        if (old == GRID - 1) {
            g_bar = 0;               // reset for next replay
            __threadfence();
            atomicAdd(&g_gen, 1u);   // release everyone
        } else {
            while (*(volatile unsigned int*)&g_gen == start) { }
        }
        bar_gen = 1;
    }
    __syncthreads();
    __threadfence();                 // acquire side
    (void)bar_gen;

    // ---------------- Phase 2: cp.async-staged element energy ------------
    unsigned int gb = (unsigned int)__cvta_generic_to_shared(gbuf);
    const unsigned int my_base = gb + threadIdx.x * 16u;   // [k][tid] layout

    // Issue iteration-0 gathers into stage 0.
    {
        unsigned int b0 = my_base;                 // stage 0
        cp_async16(b0 + 0u * TPB * 16u, &g_pred4[s_cur.cab.x]);
        cp_async16(b0 + 1u * TPB * 16u, &g_pred4[s_cur.cab.y]);
        cp_async16(b0 + 2u * TPB * 16u, &g_pred4[s_cur.cab.z]);
        cp_async16(b0 + 3u * TPB * 16u, &g_pred4[s_cur.cab.w]);
        asm volatile("cp.async.commit_group;");
    }

    float facc = 0.0f;

    #pragma unroll
    for (int i = 0; i < NITER; i++) {
        // Issue next iteration's gathers (stage (i+1)&1) before waiting.
        if (i + 1 < NITER) {
            unsigned int bn = my_base + (unsigned int)(((i + 1) & 1) * 4 * TPB) * 16u;
            cp_async16(bn + 0u * TPB * 16u, &g_pred4[s_nxt.cab.x]);
            cp_async16(bn + 1u * TPB * 16u, &g_pred4[s_nxt.cab.y]);
            cp_async16(bn + 2u * TPB * 16u, &g_pred4[s_nxt.cab.z]);
            cp_async16(bn + 3u * TPB * 16u, &g_pred4[s_nxt.cab.w]);
            asm volatile("cp.async.commit_group;");
        }

        Stream s_aft;
        if (i + 2 < NITER)
            s_aft = load_stream(tid + (i + 2) * NTH,
                                c4, L2p, E2p, A2p, I2p, d2p);

        // Complete group i (leave the newest group in flight).
        if (i + 1 < NITER)
            asm volatile("cp.async.wait_group 1;" ::: "memory");
        else
            asm volatile("cp.async.wait_group 0;" ::: "memory");

        // Read own slots from stage i&1 (no block sync needed).
        Gath G;
        {
            int sb = (i & 1) * 4 * TPB + threadIdx.x;
            G.A0 = gbuf[sb + 0 * TPB];
            G.B0 = gbuf[sb + 1 * TPB];
            G.A1 = gbuf[sb + 2 * TPB];
            G.B1 = gbuf[sb + 3 * TPB];
        }

        facc += pair_energy(s_cur, G);

        s_cur = s_nxt;
        if (i + 2 < NITER) s_nxt = s_aft;
    }

    acc += 0.5 * (double)facc;

    // ---------------- Final reduction ------------------------------------
    double bsum = block_reduce_add(acc);

    __shared__ bool is_last;
    if (threadIdx.x == 0) {
        g_partials[blockIdx.x] = bsum;
        __threadfence();
        unsigned int done = atomicAdd(&g_count, 1u);
        is_last = (done == GRID - 1);
    }
    __syncthreads();

    if (is_last) {
        double v = 0.0;
        for (int b = threadIdx.x; b < GRID; b += TPB)
            v += g_partials[b];
        double total = block_reduce_add(v);
        if (threadIdx.x == 0) {
            double E_c = fmax((double)__ldg(F_c_p) * (double)u_c, 1e-30);
            out[0] = (float)(total / E_c);
            __threadfence();
            g_count = 0;  // replay-safe reset
        }
    }
}

extern "C" void kernel_launch(void* const* d_in, const int* in_sizes, int n_in,
                              void* d_out, int out_size) {
    const float* pred  = (const float*)d_in[0];
    const float* Lv    = (const float*)d_in[1];
    const float* Ev    = (const float*)d_in[2];
    const float* Av    = (const float*)d_in[3];
    const float* Iv    = (const float*)d_in[4];
    const float* dir   = (const float*)d_in[5];
    const float* Fext  = (const float*)d_in[6];
    const float* u_c   = (const float*)d_in[7];
    const float* th_c  = (const float*)d_in[8];
    const float* F_c   = (const float*)d_in[9];
    const int*   conn  = (const int*)d_in[10];
    float* out = (float*)d_out;

    fused_energy_kernel<<<GRID, TPB>>>(
        pred, Lv, Ev, Av, Iv, dir, conn, Fext, u_c, th_c, F_c, out);
}

// round 14
// speedup vs baseline: 1.3138x; 1.3138x over previous
#include <cuda_runtime.h>
#include <cuda_bf16.h>
#include <cstdint>

#define N_NODES 500000
#define N_ELEM  1000000
#define N_G4    (N_ELEM / 4)          // 250000 groups of 4 elements
#define N_NG4   (N_NODES / 4)         // 125000 node groups of 4

#define TPB   256
#define GRID  296                     // 148 SMs * 2 blocks -> all co-resident
#define NTH   (GRID * TPB)            // 75776 threads
#define NITER ((N_G4 + NTH - 1) / NTH) // 4 (compile-time)

// Packed, pre-scaled node displacements (u_phys), 16B/node.
__device__ float4 g_pred4[N_NODES];               // 8 MB scratch
__device__ double g_partials[GRID];
__device__ unsigned int g_bar;    // barrier arrive counter (reset in-kernel)
__device__ unsigned int g_gen;    // barrier generation (monotonic across replays)
__device__ unsigned int g_count;  // finalize counter (reset in-kernel)

__device__ __forceinline__ double block_reduce_add(double v) {
    __shared__ double warp_sums[TPB / 32];
    int lane = threadIdx.x & 31;
    int wid  = threadIdx.x >> 5;

    #pragma unroll
    for (int off = 16; off > 0; off >>= 1)
        v += __shfl_down_sync(0xFFFFFFFFu, v, off);

    if (lane == 0) warp_sums[wid] = v;
    __syncthreads();

    v = (threadIdx.x < (TPB / 32)) ? warp_sums[threadIdx.x] : 0.0;
    if (wid == 0) {
        #pragma unroll
        for (int off = (TPB / 64); off > 0; off >>= 1)
            v += __shfl_down_sync(0xFFFFFFFFu, v, off);
    }
    __syncthreads();
    return v; // valid in thread 0
}

__device__ __forceinline__ float one_elem(
    float c, float s, float4 PA, float4 PB,
    float L, float E, float A, float I)
{
    float uA =  c * PA.x + s * PA.y;
    float wA = -s * PA.x + c * PA.y;
    float uB =  c * PB.x + s * PB.y;
    float wB = -s * PB.x + c * PB.y;
    float tA = PA.z, tB = PB.z;

    float EA = E * A;
    float EI = E * I;
    float invL  = 1.0f / L;
    float ea_L  = EA * invL;
    float ei_L  = EI * invL;
    float ei_L2 = ei_L * invL;
    float ei_L3 = ei_L2 * invL;

    float du = uA - uB;
    float dw = wA - wB;
    float ts = tA + tB;

    return ea_L * du * du
         + 12.0f * ei_L3 * dw * dw
         + 12.0f * ei_L2 * dw * ts
         + 4.0f  * ei_L  * (tA * tA + tB * tB + tA * tB);
}

__global__ void __launch_bounds__(TPB, 2)
fused_energy_kernel(
    const float* __restrict__ pred,   // [N_NODES,3]
    const float* __restrict__ Lv,
    const float* __restrict__ Ev,
    const float* __restrict__ Av,
    const float* __restrict__ Iv,
    const float* __restrict__ dir,    // [N_ELEM,3]
    const int*   __restrict__ conn,   // [N_ELEM,2]
    const float* __restrict__ Fext,   // [N_NODES,3]
    const float* __restrict__ u_c_p,
    const float* __restrict__ th_c_p,
    const float* __restrict__ F_c_p,
    float*       __restrict__ out)
{
    const float u_c  = __ldg(u_c_p);
    const float th_c = __ldg(th_c_p);

    const int tid = blockIdx.x * TPB + threadIdx.x;

    double acc = 0.0;   // -W_ext contribution; energy added at end

    // ---------------- Phase 1: pack nodes + external work ----------------
    {
        const float4* p4 = (const float4*)pred;
        const float4* f4 = (const float4*)Fext;

        for (int t = tid; t < N_NG4; t += NTH) {
            float4 P0 = __ldg(&p4[3 * t + 0]);  // x0 y0 t0 x1
            float4 P1 = __ldg(&p4[3 * t + 1]);  // y1 t1 x2 y2
            float4 P2 = __ldg(&p4[3 * t + 2]);  // t2 x3 y3 t3
            float4 F0 = __ldg(&f4[3 * t + 0]);
            float4 F1 = __ldg(&f4[3 * t + 1]);
            float4 F2 = __ldg(&f4[3 * t + 2]);

            float4 n0 = make_float4(P0.x * u_c, P0.y * u_c, P0.z * th_c, 0.0f);
            float4 n1 = make_float4(P0.w * u_c, P1.x * u_c, P1.y * th_c, 0.0f);
            float4 n2 = make_float4(P1.z * u_c, P1.w * u_c, P2.x * th_c, 0.0f);
            float4 n3 = make_float4(P2.y * u_c, P2.z * u_c, P2.w * th_c, 0.0f);

            int n = 4 * t;
            g_pred4[n + 0] = n0;
            g_pred4[n + 1] = n1;
            g_pred4[n + 2] = n2;
            g_pred4[n + 3] = n3;

            float w = F0.x * n0.x + F0.y * n0.y + F0.z * n0.z
                    + F0.w * n1.x + F1.x * n1.y + F1.y * n1.z
                    + F1.z * n2.x + F1.w * n2.y + F2.x * n2.z
                    + F2.y * n3.x + F2.z * n3.y + F2.w * n3.z;
            acc -= (double)w;
        }
    }

    // ---------------- Grid-wide barrier (all 296 blocks co-resident) -----
    __syncthreads();                 // whole block done with phase-1 stores
    __shared__ unsigned int bar_gen;
    if (threadIdx.x == 0) {
        __threadfence();             // publish g_pred4 stores to L2
        unsigned int start = *(volatile unsigned int*)&g_gen;
        unsigned int old = atomicAdd(&g_bar, 1u);
        if (old == GRID - 1) {
            g_bar = 0;               // reset for next replay
            __threadfence();
            atomicAdd(&g_gen, 1u);   // release everyone
        } else {
            while (*(volatile unsigned int*)&g_gen == start) { }
        }
        bar_gen = 1;
    }
    __syncthreads();
    __threadfence();                 // acquire side
    (void)bar_gen;

    // ---------------- Phase 2: 4 elements/thread/iter, max-width loads ---
    // Memory instructions per group of 4 elements:
    //   2x int4 (conn) + 4x float4 (L,E,A,I) + 3x float4 (dir) + 8x float4 gather
    const int4*   c4 = (const int4*)conn;
    const float4* L4 = (const float4*)Lv;
    const float4* E4 = (const float4*)Ev;
    const float4* A4 = (const float4*)Av;
    const float4* I4 = (const float4*)Iv;
    const float4* d4 = (const float4*)dir;

    float facc = 0.0f;

    #pragma unroll
    for (int i = 0; i < NITER; i++) {
        int g = tid + i * NTH;
        if (g < N_G4) {
            // Front-batch all stream loads (independent)
            int4 cab0 = __ldg(&c4[2 * g + 0]);   // nA0,nB0,nA1,nB1
            int4 cab1 = __ldg(&c4[2 * g + 1]);   // nA2,nB2,nA3,nB3
            float4 Lq = __ldg(&L4[g]);
            float4 Eq = __ldg(&E4[g]);
            float4 Aq = __ldg(&A4[g]);
            float4 Iq = __ldg(&I4[g]);
            float4 D0 = __ldg(&d4[3 * g + 0]);   // c0,0,s0,c1
            float4 D1 = __ldg(&d4[3 * g + 1]);   // 0,s1,c2,0
            float4 D2 = __ldg(&d4[3 * g + 2]);   // s2,c3,0,s3

            // 8 coherent 16B gathers (g_pred4 written this launch -> no __ldg)
            float4 PA0 = g_pred4[cab0.x];
            float4 PB0 = g_pred4[cab0.y];
            float4 PA1 = g_pred4[cab0.z];
            float4 PB1 = g_pred4[cab0.w];
            float4 PA2 = g_pred4[cab1.x];
            float4 PB2 = g_pred4[cab1.y];
            float4 PA3 = g_pred4[cab1.z];
            float4 PB3 = g_pred4[cab1.w];

            facc += one_elem(D0.x, D0.z, PA0, PB0, Lq.x, Eq.x, Aq.x, Iq.x);
            facc += one_elem(D0.w, D1.y, PA1, PB1, Lq.y, Eq.y, Aq.y, Iq.y);
            facc += one_elem(D1.z, D2.x, PA2, PB2, Lq.z, Eq.z, Aq.z, Iq.z);
            facc += one_elem(D2.y, D2.w, PA3, PB3, Lq.w, Eq.w, Aq.w, Iq.w);
        }
    }

    acc += 0.5 * (double)facc;

    // ---------------- Final reduction ------------------------------------
    double bsum = block_reduce_add(acc);

    __shared__ bool is_last;
    if (threadIdx.x == 0) {
        g_partials[blockIdx.x] = bsum;
        __threadfence();
        unsigned int done = atomicAdd(&g_count, 1u);
        is_last = (done == GRID - 1);
    }
    __syncthreads();

    if (is_last) {
        double v = 0.0;
        for (int b = threadIdx.x; b < GRID; b += TPB)
            v += g_partials[b];
        double total = block_reduce_add(v);
        if (threadIdx.x == 0) {
            double E_c = fmax((double)__ldg(F_c_p) * (double)u_c, 1e-30);
            out[0] = (float)(total / E_c);
            __threadfence();
            g_count = 0;  // replay-safe reset
        }
    }
}

extern "C" void kernel_launch(void* const* d_in, const int* in_sizes, int n_in,
                              void* d_out, int out_size) {
    const float* pred  = (const float*)d_in[0];
    const float* Lv    = (const float*)d_in[1];
    const float* Ev    = (const float*)d_in[2];
    const float* Av    = (const float*)d_in[3];
    const float* Iv    = (const float*)d_in[4];
    const float* dir   = (const float*)d_in[5];
    const float* Fext  = (const float*)d_in[6];
    const float* u_c   = (const float*)d_in[7];
    const float* th_c  = (const float*)d_in[8];
    const float* F_c   = (const float*)d_in[9];
    const int*   conn  = (const int*)d_in[10];
    float* out = (float*)d_out;

    fused_energy_kernel<<<GRID, TPB>>>(
        pred, Lv, Ev, Av, Iv, dir, conn, Fext, u_c, th_c, F_c, out);
}

// round 15
// speedup vs baseline: 1.3516x; 1.0288x over previous
#include <cuda_runtime.h>
#include <cuda_bf16.h>
#include <cstdint>

#define N_NODES 500000
#define N_ELEM  1000000
#define N_G2    (N_ELEM / 2)          // 500000 element pairs
#define N_NG4   (N_NODES / 4)         // 125000 node groups of 4

#define TPB   256
#define GRID  296                     // 148 SMs * 2 blocks -> all co-resident
#define NTH   (GRID * TPB)            // 75776 threads
#define NITER ((N_G2 + NTH - 1) / NTH) // 7 (compile-time)

// Packed, pre-scaled node displacements (u_phys), 16B/node.
__device__ float4 g_pred4[N_NODES];               // 8 MB scratch
__device__ double g_partials[GRID];
__device__ unsigned int g_bar;    // barrier arrive counter (reset in-kernel)
__device__ unsigned int g_gen;    // barrier generation (monotonic across replays)
__device__ unsigned int g_count;  // finalize counter (reset in-kernel)

__device__ __forceinline__ double block_reduce_add(double v) {
    __shared__ double warp_sums[TPB / 32];
    int lane = threadIdx.x & 31;
    int wid  = threadIdx.x >> 5;

    #pragma unroll
    for (int off = 16; off > 0; off >>= 1)
        v += __shfl_down_sync(0xFFFFFFFFu, v, off);

    if (lane == 0) warp_sums[wid] = v;
    __syncthreads();

    v = (threadIdx.x < (TPB / 32)) ? warp_sums[threadIdx.x] : 0.0;
    if (wid == 0) {
        #pragma unroll
        for (int off = (TPB / 64); off > 0; off >>= 1)
            v += __shfl_down_sync(0xFFFFFFFFu, v, off);
    }
    __syncthreads();
    return v; // valid in thread 0
}

// ---- element-phase structs / helpers ----
struct Stream {
    int4   cab;          // nA0,nB0,nA1,nB1
    float2 L, E, A, I;
    float2 D0, D1, D2;   // (c0,0) (s0,c1) (0,s1)
    float  w;            // validity mask
};
struct Gath { float4 A0, B0, A1, B1; };

__device__ __forceinline__ Stream load_stream(
    int g,
    const int4* __restrict__ c4,
    const float2* __restrict__ L2p, const float2* __restrict__ E2p,
    const float2* __restrict__ A2p, const float2* __restrict__ I2p,
    const float2* __restrict__ d2p)
{
    Stream S;
    bool v = (g < N_G2);
    int gg = v ? g : 0;
    S.cab = __ldg(&c4[gg]);
    S.L   = __ldg(&L2p[gg]);
    S.E   = __ldg(&E2p[gg]);
    S.A   = __ldg(&A2p[gg]);
    S.I   = __ldg(&I2p[gg]);
    S.D0  = __ldg(&d2p[3 * gg + 0]);
    S.D1  = __ldg(&d2p[3 * gg + 1]);
    S.D2  = __ldg(&d2p[3 * gg + 2]);
    S.w   = v ? 1.0f : 0.0f;
    return S;
}

// Gather with ld.global.cg: L2-coherent (g_pred4 was written this launch)
// and bypasses L1 -> no stale-L1 risk, no L1 allocation cost.
__device__ __forceinline__ float4 ldcg_f4(const float4* p) {
    float4 r;
    asm volatile("ld.global.cg.v4.f32 {%0,%1,%2,%3}, [%4];"
                 : "=f"(r.x), "=f"(r.y), "=f"(r.z), "=f"(r.w)
                 : "l"(p));
    return r;
}

__device__ __forceinline__ Gath load_gather(const int4 cab) {
    Gath G;
    G.A0 = ldcg_f4(&g_pred4[cab.x]);
    G.B0 = ldcg_f4(&g_pred4[cab.y]);
    G.A1 = ldcg_f4(&g_pred4[cab.z]);
    G.B1 = ldcg_f4(&g_pred4[cab.w]);
    return G;
}

__device__ __forceinline__ float one_elem(
    float c, float s, float4 PA, float4 PB,
    float L, float E, float A, float I)
{
    float uA =  c * PA.x + s * PA.y;
    float wA = -s * PA.x + c * PA.y;
    float uB =  c * PB.x + s * PB.y;
    float wB = -s * PB.x + c * PB.y;
    float tA = PA.z, tB = PB.z;

    float EA = E * A;
    float EI = E * I;
    float invL  = 1.0f / L;
    float ea_L  = EA * invL;
    float ei_L  = EI * invL;
    float ei_L2 = ei_L * invL;
    float ei_L3 = ei_L2 * invL;

    float du = uA - uB;
    float dw = wA - wB;
    float ts = tA + tB;

    return ea_L * du * du
         + 12.0f * ei_L3 * dw * dw
         + 12.0f * ei_L2 * dw * ts
         + 4.0f  * ei_L  * (tA * tA + tB * tB + tA * tB);
}

__device__ __forceinline__ float pair_energy(const Stream& S, const Gath& G) {
    float q = one_elem(S.D0.x, S.D1.x, G.A0, G.B0, S.L.x, S.E.x, S.A.x, S.I.x)
            + one_elem(S.D1.y, S.D2.y, G.A1, G.B1, S.L.y, S.E.y, S.A.y, S.I.y);
    return q * S.w;
}

__global__ void __launch_bounds__(TPB, 2)
fused_energy_kernel(
    const float* __restrict__ pred,   // [N_NODES,3]
    const float* __restrict__ Lv,
    const float* __restrict__ Ev,
    const float* __restrict__ Av,
    const float* __restrict__ Iv,
    const float* __restrict__ dir,    // [N_ELEM,3]
    const int*   __restrict__ conn,   // [N_ELEM,2]
    const float* __restrict__ Fext,   // [N_NODES,3]
    const float* __restrict__ u_c_p,
    const float* __restrict__ th_c_p,
    const float* __restrict__ F_c_p,
    float*       __restrict__ out)
{
    const float u_c  = __ldg(u_c_p);
    const float th_c = __ldg(th_c_p);

    const int tid = blockIdx.x * TPB + threadIdx.x;

    double acc = 0.0;   // -W_ext contribution; energy added at end

    // ---------------- Phase 1: pack nodes + external work ----------------
    {
        const float4* p4 = (const float4*)pred;
        const float4* f4 = (const float4*)Fext;

        for (int t = tid; t < N_NG4; t += NTH) {
            float4 P0 = __ldg(&p4[3 * t + 0]);  // x0 y0 t0 x1
            float4 P1 = __ldg(&p4[3 * t + 1]);  // y1 t1 x2 y2
            float4 P2 = __ldg(&p4[3 * t + 2]);  // t2 x3 y3 t3
            float4 F0 = __ldg(&f4[3 * t + 0]);
            float4 F1 = __ldg(&f4[3 * t + 1]);
            float4 F2 = __ldg(&f4[3 * t + 2]);

            float4 n0 = make_float4(P0.x * u_c, P0.y * u_c, P0.z * th_c, 0.0f);
            float4 n1 = make_float4(P0.w * u_c, P1.x * u_c, P1.y * th_c, 0.0f);
            float4 n2 = make_float4(P1.z * u_c, P1.w * u_c, P2.x * th_c, 0.0f);
            float4 n3 = make_float4(P2.y * u_c, P2.z * u_c, P2.w * th_c, 0.0f);

            int n = 4 * t;
            g_pred4[n + 0] = n0;
            g_pred4[n + 1] = n1;
            g_pred4[n + 2] = n2;
            g_pred4[n + 3] = n3;

            float w = F0.x * n0.x + F0.y * n0.y + F0.z * n0.z
                    + F0.w * n1.x + F1.x * n1.y + F1.y * n1.z
                    + F1.z * n2.x + F1.w * n2.y + F2.x * n2.z
                    + F2.y * n3.x + F2.z * n3.y + F2.w * n3.z;
            acc -= (double)w;
        }
    }

    // ---------------- Prefetch phase-2 streams (pack-independent) --------
    const int4*   c4  = (const int4*)conn;
    const float2* L2p = (const float2*)Lv;
    const float2* E2p = (const float2*)Ev;
    const float2* A2p = (const float2*)Av;
    const float2* I2p = (const float2*)Iv;
    const float2* d2p = (const float2*)dir;

    Stream s_cur = load_stream(tid,       c4, L2p, E2p, A2p, I2p, d2p);
    Stream s_nxt = load_stream(tid + NTH, c4, L2p, E2p, A2p, I2p, d2p);

    // ---------------- Grid-wide barrier (all 296 blocks co-resident) -----
    __syncthreads();                 // whole block done with phase-1 stores
    __shared__ unsigned int bar_gen;
    if (threadIdx.x == 0) {
        __threadfence();             // publish g_pred4 stores to L2
        unsigned int start = *(volatile unsigned int*)&g_gen;
        unsigned int old = atomicAdd(&g_bar, 1u);
        if (old == GRID - 1) {
            g_bar = 0;               // reset for next replay
            __threadfence();
            atomicAdd(&g_gen, 1u);   // release everyone
        } else {
            while (*(volatile unsigned int*)&g_gen == start) { }
        }
        bar_gen = 1;
    }
    __syncthreads();
    __threadfence();                 // acquire side
    (void)bar_gen;

    // ---------------- Phase 2: pipelined element energy ------------------
    float facc = 0.0f;
    Gath g_cur = load_gather(s_cur.cab);

    #pragma unroll
    for (int i = 0; i < NITER; i++) {
        Gath   g_nxt;
        Stream s_aft;
        if (i + 1 < NITER)
            g_nxt = load_gather(s_nxt.cab);            // cab arrived 1 iter ago
        if (i + 2 < NITER)
            s_aft = load_stream(tid + (i + 2) * NTH,
                                c4, L2p, E2p, A2p, I2p, d2p);

        facc += pair_energy(s_cur, g_cur);             // overlaps in-flight loads

        s_cur = s_nxt;
        if (i + 2 < NITER) s_nxt = s_aft;
        if (i + 1 < NITER) g_cur = g_nxt;
    }

    acc += 0.5 * (double)facc;

    // ---------------- Final reduction ------------------------------------
    double bsum = block_reduce_add(acc);

    __shared__ bool is_last;
    if (threadIdx.x == 0) {
        g_partials[blockIdx.x] = bsum;
        __threadfence();
        unsigned int done = atomicAdd(&g_count, 1u);
        is_last = (done == GRID - 1);
    }
    __syncthreads();

    if (is_last) {
        double v = 0.0;
        for (int b = threadIdx.x; b < GRID; b += TPB)
            v += g_partials[b];
        double total = block_reduce_add(v);
        if (threadIdx.x == 0) {
            double E_c = fmax((double)__ldg(F_c_p) * (double)u_c, 1e-30);
            out[0] = (float)(total / E_c);
            __threadfence();
            g_count = 0;  // replay-safe reset
        }
    }
}

extern "C" void kernel_launch(void* const* d_in, const int* in_sizes, int n_in,
                              void* d_out, int out_size) {
    const float* pred  = (const float*)d_in[0];
    const float* Lv    = (const float*)d_in[1];
    const float* Ev    = (const float*)d_in[2];
    const float* Av    = (const float*)d_in[3];
    const float* Iv    = (const float*)d_in[4];
    const float* dir   = (const float*)d_in[5];
    const float* Fext  = (const float*)d_in[6];
    const float* u_c   = (const float*)d_in[7];
    const float* th_c  = (const float*)d_in[8];
    const float* F_c   = (const float*)d_in[9];
    const int*   conn  = (const int*)d_in[10];
    float* out = (float*)d_out;

    fused_energy_kernel<<<GRID, TPB>>>(
        pred, Lv, Ev, Av, Iv, dir, conn, Fext, u_c, th_c, F_c, out);
}